// round 1
// baseline (speedup 1.0000x reference)
#include <cuda_runtime.h>

// Problem constants (fixed by the reference)
#define BB 16
#define CC 3
#define TT 16
#define HH 224
#define WW 224
#define W4 (WW / 4)                     // 56 float4 per row
#define COLOR_STRENGTH 0.3f
#define NOISE_STRENGTH 0.02f
#define DROPOUT_PROB 0.05f
#define HFLIP_PROB 0.5f
#define MAX_JITTER 3

static const long long TOTAL4 = (long long)BB * CC * TT * HH * W4;  // 9,633,792

// Per-batch precomputed parameters (allocation-free scratch)
__device__ float g_bf[BB];
__device__ float g_cf[BB];
__device__ int   g_flip[BB];
__device__ int   g_j[BB];
__device__ float g_keep[BB * TT];

__global__ void precompute_params(const int* __restrict__ jitter,
                                  const float* __restrict__ b_rand,
                                  const float* __restrict__ c_rand,
                                  const float* __restrict__ flip_rand,
                                  const float* __restrict__ drop_rand) {
    int b = threadIdx.x;
    if (b >= BB) return;

    g_bf[b] = 1.0f + (b_rand[b] - 0.5f) * 2.0f * COLOR_STRENGTH;

    float cf = 1.0f + (c_rand[b] - 0.5f) * 2.0f * COLOR_STRENGTH;
    g_cf[b] = fminf(fmaxf(cf, 0.1f), 3.0f);

    g_flip[b] = (flip_rand[b] < HFLIP_PROB) ? 1 : 0;
    g_j[b] = jitter[b] - MAX_JITTER;

    bool k[TT];
    bool any = false;
    #pragma unroll
    for (int t = 0; t < TT; ++t) {
        k[t] = drop_rand[b * TT + t] > DROPOUT_PROB;
        any |= k[t];
    }
    if (!any) k[0] = true;
    #pragma unroll
    for (int t = 0; t < TT; ++t) {
        g_keep[b * TT + t] = k[t] ? 1.0f : 0.0f;
    }
}

__device__ __forceinline__ float clamp01(float x) {
    return fminf(fmaxf(x, 0.0f), 1.0f);
}

__device__ __forceinline__ float aug_one(float v, float n, float bf, float cf) {
    float x = clamp01(v * bf);                     // brightness
    x = clamp01((x - 0.5f) * cf + 0.5f);           // contrast
    x = clamp01(x + n * NOISE_STRENGTH);           // noise
    return x;
}

__global__ void __launch_bounds__(256)
augment_kernel(const float4* __restrict__ video,
               const float4* __restrict__ noise,
               float4* __restrict__ out) {
    long long i = (long long)blockIdx.x * blockDim.x + threadIdx.x;
    if (i >= (long long)BB * CC * TT * HH * W4) return;

    // decode (b, c, t, h, w4) from linear float4 index
    int w4 = (int)(i % W4);
    long long r = i / W4;
    int h = (int)(r % HH); r /= HH;
    int t = (int)(r % TT); r /= TT;
    int c = (int)(r % CC);
    int b = (int)(r / CC);

    int flip = g_flip[b];
    int j = g_j[b];
    int tsrc = t - j;                  // j in [-3,3], t in [0,15] => tsrc in [-3,18]
    if (tsrc < 0)   tsrc += TT;
    if (tsrc >= TT) tsrc += -TT;

    int wsrc4 = flip ? (W4 - 1 - w4) : w4;

    size_t plane = (size_t)HH * W4;
    size_t bc = ((size_t)b * CC + c) * TT;
    size_t vidx = (bc + tsrc) * plane + (size_t)h * W4 + wsrc4;
    size_t nidx = (bc + t)    * plane + (size_t)h * W4 + wsrc4;

    float4 v = video[vidx];
    float4 n = noise[nidx];

    if (flip) {
        float tmp;
        tmp = v.x; v.x = v.w; v.w = tmp;
        tmp = v.y; v.y = v.z; v.z = tmp;
        tmp = n.x; n.x = n.w; n.w = tmp;
        tmp = n.y; n.y = n.z; n.z = tmp;
    }

    float bf = g_bf[b];
    float cf = g_cf[b];
    float kp = g_keep[b * TT + t];

    float4 o;
    o.x = aug_one(v.x, n.x, bf, cf) * kp;
    o.y = aug_one(v.y, n.y, bf, cf) * kp;
    o.z = aug_one(v.z, n.z, bf, cf) * kp;
    o.w = aug_one(v.w, n.w, bf, cf) * kp;

    out[i] = o;
}

extern "C" void kernel_launch(void* const* d_in, const int* in_sizes, int n_in,
                              void* d_out, int out_size) {
    // metadata order: video, jitter, b_rand, c_rand, noise, flip_rand, drop_rand
    const float* video     = (const float*)d_in[0];
    const int*   jitter    = (const int*)d_in[1];
    const float* b_rand    = (const float*)d_in[2];
    const float* c_rand    = (const float*)d_in[3];
    const float* noise     = (const float*)d_in[4];
    const float* flip_rand = (const float*)d_in[5];
    const float* drop_rand = (const float*)d_in[6];
    float* out = (float*)d_out;

    precompute_params<<<1, BB>>>(jitter, b_rand, c_rand, flip_rand, drop_rand);

    long long total4 = (long long)BB * CC * TT * HH * W4;
    int threads = 256;
    int blocks = (int)((total4 + threads - 1) / threads);
    augment_kernel<<<blocks, threads>>>((const float4*)video,
                                        (const float4*)noise,
                                        (float4*)out);
}

// round 2
// speedup vs baseline: 1.0482x; 1.0482x over previous
#include <cuda_runtime.h>

// Problem constants (fixed by the reference)
#define BB 16
#define CC 3
#define TT 16
#define HH 224
#define WW 224
#define W4 (WW / 4)                     // 56 float4 per row
#define PLANE4 (HH * W4)                // 12544 float4 per (b,c,t) plane
#define COLOR_STRENGTH 0.3f
#define NOISE_STRENGTH 0.02f
#define DROPOUT_PROB 0.05f
#define HFLIP_PROB 0.5f
#define MAX_JITTER 3

__device__ __forceinline__ float clamp01(float x) {
    return fminf(fmaxf(x, 0.0f), 1.0f);
}

__device__ __forceinline__ float aug_one(float v, float n, float bf, float cf) {
    float x = clamp01(v * bf);                     // brightness
    x = clamp01((x - 0.5f) * cf + 0.5f);           // contrast
    x = clamp01(x + n * NOISE_STRENGTH);           // noise
    return x;
}

__global__ void __launch_bounds__(256)
augment_fused(const float4* __restrict__ video,
              const float4* __restrict__ noise,
              float4* __restrict__ out,
              const int*   __restrict__ jitter,
              const float* __restrict__ b_rand,
              const float* __restrict__ c_rand,
              const float* __restrict__ flip_rand,
              const float* __restrict__ drop_rand) {
    // blockIdx.y encodes (b, c, t); all divisors compile-time constants.
    const int bct = blockIdx.y;                 // [0, 768)
    const int t   = bct % TT;
    const int bc  = bct / TT;                   // b*CC + c
    const int b   = bc / CC;

    // ---- block-uniform per-batch params (broadcast L1 loads) ----
    const float bf   = 1.0f + (b_rand[b] - 0.5f) * 2.0f * COLOR_STRENGTH;
    float cf         = 1.0f + (c_rand[b] - 0.5f) * 2.0f * COLOR_STRENGTH;
    cf = fminf(fmaxf(cf, 0.1f), 3.0f);
    const bool flip  = flip_rand[b] < HFLIP_PROB;
    const int  j     = jitter[b] - MAX_JITTER;  // [-3, 3]
    const int  tsrc  = (t - j + TT) & (TT - 1); // roll source frame

    bool kp = drop_rand[b * TT + t] > DROPOUT_PROB;
    if (t == 0 && !kp) {
        // guarantee >=1 kept frame: if nothing kept, frame 0 is kept
        bool any = false;
        #pragma unroll
        for (int t2 = 1; t2 < TT; ++t2)
            any |= (drop_rand[b * TT + t2] > DROPOUT_PROB);
        kp = !any;
    }

    // ---- in-plane position (32-bit, constant divisor) ----
    const int ip  = blockIdx.x * 256 + threadIdx.x;   // [0, 12544)
    const int h   = ip / W4;
    const int w4  = ip - h * W4;

    const int oidx = bct * PLANE4 + ip;

    if (!kp) {
        // dropped frame: no reads, store zeros (block-uniform branch)
        out[oidx] = make_float4(0.0f, 0.0f, 0.0f, 0.0f);
        return;
    }

    const int wsrc4 = flip ? (W4 - 1 - w4) : w4;
    const int vidx  = (bc * TT + tsrc) * PLANE4 + h * W4 + wsrc4;
    const int nidx  = bct * PLANE4 + h * W4 + wsrc4;

    // streaming loads: every source element is touched exactly once
    float4 v = __ldcs(&video[vidx]);
    float4 n = __ldcs(&noise[nidx]);

    if (flip) {
        float tmp;
        tmp = v.x; v.x = v.w; v.w = tmp;
        tmp = v.y; v.y = v.z; v.z = tmp;
        tmp = n.x; n.x = n.w; n.w = tmp;
        tmp = n.y; n.y = n.z; n.z = tmp;
    }

    float4 o;
    o.x = aug_one(v.x, n.x, bf, cf);
    o.y = aug_one(v.y, n.y, bf, cf);
    o.z = aug_one(v.z, n.z, bf, cf);
    o.w = aug_one(v.w, n.w, bf, cf);

    __stcs(&out[oidx], o);   // write-once output, don't pollute L2
}

extern "C" void kernel_launch(void* const* d_in, const int* in_sizes, int n_in,
                              void* d_out, int out_size) {
    // metadata order: video, jitter, b_rand, c_rand, noise, flip_rand, drop_rand
    const float* video     = (const float*)d_in[0];
    const int*   jitter    = (const int*)d_in[1];
    const float* b_rand    = (const float*)d_in[2];
    const float* c_rand    = (const float*)d_in[3];
    const float* noise     = (const float*)d_in[4];
    const float* flip_rand = (const float*)d_in[5];
    const float* drop_rand = (const float*)d_in[6];
    float* out = (float*)d_out;

    dim3 grid(PLANE4 / 256, BB * CC * TT);   // (49, 768)
    augment_fused<<<grid, 256>>>((const float4*)video,
                                 (const float4*)noise,
                                 (float4*)out,
                                 jitter, b_rand, c_rand, flip_rand, drop_rand);
}

// round 3
// speedup vs baseline: 1.0487x; 1.0005x over previous
#include <cuda_runtime.h>

// Problem constants (fixed by the reference)
#define BB 16
#define CC 3
#define TT 16
#define HH 224
#define WW 224
#define W4 (WW / 4)                     // 56 float4 per row
#define PLANE4 (HH * W4)                // 12544 float4 per (b,c,t) plane
#define COLOR_STRENGTH 0.3f
#define NOISE_STRENGTH 0.02f
#define DROPOUT_PROB 0.05f
#define HFLIP_PROB 0.5f
#define MAX_JITTER 3

#define THREADS 256
#define ILP 2
#define BLK_ELEMS (THREADS * ILP)       // 512 float4 per block
#define GRID_X ((PLANE4 + BLK_ELEMS - 1) / BLK_ELEMS)  // 25

__device__ __forceinline__ float clamp01(float x) {
    return fminf(fmaxf(x, 0.0f), 1.0f);
}

__device__ __forceinline__ float aug_one(float v, float n, float bf, float cf) {
    float x = clamp01(v * bf);                     // brightness
    x = clamp01((x - 0.5f) * cf + 0.5f);           // contrast
    x = clamp01(x + n * NOISE_STRENGTH);           // noise
    return x;
}

__global__ void __launch_bounds__(THREADS)
augment_fused(const float4* __restrict__ video,
              const float4* __restrict__ noise,
              float4* __restrict__ out,
              const int*   __restrict__ jitter,
              const float* __restrict__ b_rand,
              const float* __restrict__ c_rand,
              const float* __restrict__ flip_rand,
              const float* __restrict__ drop_rand) {
    // blockIdx.y encodes (b, c, t); all divisors compile-time constants.
    const int bct = blockIdx.y;                 // [0, 768)
    const int t   = bct % TT;
    const int bc  = bct / TT;                   // b*CC + c
    const int b   = bc / CC;

    // ---- block-uniform per-batch params (broadcast L1 loads) ----
    const float bf   = 1.0f + (b_rand[b] - 0.5f) * 2.0f * COLOR_STRENGTH;
    float cf         = 1.0f + (c_rand[b] - 0.5f) * 2.0f * COLOR_STRENGTH;
    cf = fminf(fmaxf(cf, 0.1f), 3.0f);
    const bool flip  = flip_rand[b] < HFLIP_PROB;
    const int  j     = jitter[b] - MAX_JITTER;  // [-3, 3]
    const int  tsrc  = (t - j + TT) & (TT - 1); // roll source frame

    bool kp = drop_rand[b * TT + t] > DROPOUT_PROB;
    if (t == 0 && !kp) {
        // guarantee >=1 kept frame: if nothing kept, frame 0 is kept
        bool any = false;
        #pragma unroll
        for (int t2 = 1; t2 < TT; ++t2)
            any |= (drop_rand[b * TT + t2] > DROPOUT_PROB);
        kp = !any;
    }

    const int base = blockIdx.x * BLK_ELEMS + threadIdx.x;
    const int obase = bct * PLANE4;

    if (!kp) {
        // dropped frame: no reads, store zeros (block-uniform branch)
        #pragma unroll
        for (int u = 0; u < ILP; ++u) {
            int ip = base + u * THREADS;
            if (ip < PLANE4)
                out[obase + ip] = make_float4(0.0f, 0.0f, 0.0f, 0.0f);
        }
        return;
    }

    const int vplane = (bc * TT + tsrc) * PLANE4;

    // gather phase: get all loads in flight before any math (MLP=4)
    int ips[ILP];
    int sidx[ILP];
    bool ok[ILP];
    float4 v[ILP], n[ILP];

    #pragma unroll
    for (int u = 0; u < ILP; ++u) {
        int ip = base + u * THREADS;
        ips[u] = ip;
        ok[u] = ip < PLANE4;
        int h  = ip / W4;
        int w4 = ip - h * W4;
        int ws = flip ? (W4 - 1 - w4) : w4;
        sidx[u] = h * W4 + ws;
        if (ok[u]) v[u] = video[vplane + sidx[u]];
    }
    #pragma unroll
    for (int u = 0; u < ILP; ++u) {
        if (ok[u]) n[u] = noise[obase + sidx[u]];
    }

    #pragma unroll
    for (int u = 0; u < ILP; ++u) {
        if (!ok[u]) continue;
        float4 vv = v[u], nn = n[u];
        if (flip) {
            float tmp;
            tmp = vv.x; vv.x = vv.w; vv.w = tmp;
            tmp = vv.y; vv.y = vv.z; vv.z = tmp;
            tmp = nn.x; nn.x = nn.w; nn.w = tmp;
            tmp = nn.y; nn.y = nn.z; nn.z = tmp;
        }
        float4 o;
        o.x = aug_one(vv.x, nn.x, bf, cf);
        o.y = aug_one(vv.y, nn.y, bf, cf);
        o.z = aug_one(vv.z, nn.z, bf, cf);
        o.w = aug_one(vv.w, nn.w, bf, cf);
        out[obase + ips[u]] = o;
    }
}

extern "C" void kernel_launch(void* const* d_in, const int* in_sizes, int n_in,
                              void* d_out, int out_size) {
    // metadata order: video, jitter, b_rand, c_rand, noise, flip_rand, drop_rand
    const float* video     = (const float*)d_in[0];
    const int*   jitter    = (const int*)d_in[1];
    const float* b_rand    = (const float*)d_in[2];
    const float* c_rand    = (const float*)d_in[3];
    const float* noise     = (const float*)d_in[4];
    const float* flip_rand = (const float*)d_in[5];
    const float* drop_rand = (const float*)d_in[6];
    float* out = (float*)d_out;

    dim3 grid(GRID_X, BB * CC * TT);   // (25, 768)
    augment_fused<<<grid, THREADS>>>((const float4*)video,
                                     (const float4*)noise,
                                     (float4*)out,
                                     jitter, b_rand, c_rand, flip_rand, drop_rand);
}

// round 4
// speedup vs baseline: 1.0527x; 1.0038x over previous
#include <cuda_runtime.h>

// Problem constants (fixed by the reference)
#define BB 16
#define CC 3
#define TT 16
#define HH 224
#define WW 224
#define W4 (WW / 4)                     // 56 float4 per row
#define PLANE4 (HH * W4)                // 12544 float4 per (b,c,t) plane
#define COLOR_STRENGTH 0.3f
#define NOISE_STRENGTH 0.02f
#define DROPOUT_PROB 0.05f
#define HFLIP_PROB 0.5f
#define MAX_JITTER 3

#define THREADS 256
#define ILP 4
#define BLK_ELEMS (THREADS * ILP)       // 1024 float4 per block
#define GRID_X ((PLANE4 + BLK_ELEMS - 1) / BLK_ELEMS)  // 13 (last block partial)

__device__ __forceinline__ float clamp01(float x) {
    return fminf(fmaxf(x, 0.0f), 1.0f);
}

__device__ __forceinline__ float aug_one(float v, float n, float bf, float cf) {
    float x = clamp01(v * bf);                     // brightness
    x = clamp01((x - 0.5f) * cf + 0.5f);           // contrast
    x = clamp01(x + n * NOISE_STRENGTH);           // noise
    return x;
}

__global__ void __launch_bounds__(THREADS)
augment_fused(const float4* __restrict__ video,
              const float4* __restrict__ noise,
              float4* __restrict__ out,
              const int*   __restrict__ jitter,
              const float* __restrict__ b_rand,
              const float* __restrict__ c_rand,
              const float* __restrict__ flip_rand,
              const float* __restrict__ drop_rand) {
    // blockIdx.y encodes (b, c, t); all divisors compile-time constants.
    const int bct = blockIdx.y;                 // [0, 768)
    const int t   = bct % TT;
    const int bc  = bct / TT;                   // b*CC + c
    const int b   = bc / CC;

    // ---- block-uniform per-batch params (broadcast L1 loads) ----
    const float bf   = 1.0f + (b_rand[b] - 0.5f) * 2.0f * COLOR_STRENGTH;
    float cf         = 1.0f + (c_rand[b] - 0.5f) * 2.0f * COLOR_STRENGTH;
    cf = fminf(fmaxf(cf, 0.1f), 3.0f);
    const bool flip  = flip_rand[b] < HFLIP_PROB;
    const int  j     = jitter[b] - MAX_JITTER;  // [-3, 3]
    const int  tsrc  = (t - j + TT) & (TT - 1); // roll source frame

    bool kp = drop_rand[b * TT + t] > DROPOUT_PROB;
    if (t == 0 && !kp) {
        // guarantee >=1 kept frame: if nothing kept, frame 0 is kept
        bool any = false;
        #pragma unroll
        for (int t2 = 1; t2 < TT; ++t2)
            any |= (drop_rand[b * TT + t2] > DROPOUT_PROB);
        kp = !any;
    }

    const int base  = blockIdx.x * BLK_ELEMS + threadIdx.x;
    const int obase = bct * PLANE4;

    if (!kp) {
        // dropped frame: no reads, store zeros (block-uniform branch)
        #pragma unroll
        for (int u = 0; u < ILP; ++u) {
            int ip = base + u * THREADS;
            if (ip < PLANE4)
                out[obase + ip] = make_float4(0.0f, 0.0f, 0.0f, 0.0f);
        }
        return;
    }

    const int vplane = (bc * TT + tsrc) * PLANE4;

    // gather phase: front-batch all loads before any math (MLP = 2*ILP)
    int  ips[ILP];
    int  sidx[ILP];
    bool ok[ILP];
    float4 v[ILP], n[ILP];

    #pragma unroll
    for (int u = 0; u < ILP; ++u) {
        int ip = base + u * THREADS;
        ips[u] = ip;
        ok[u]  = ip < PLANE4;
        int h  = ip / W4;
        int w4 = ip - h * W4;
        int ws = flip ? (W4 - 1 - w4) : w4;
        sidx[u] = h * W4 + ws;
        if (ok[u]) v[u] = video[vplane + sidx[u]];
    }
    #pragma unroll
    for (int u = 0; u < ILP; ++u) {
        if (ok[u]) n[u] = noise[obase + sidx[u]];
    }

    #pragma unroll
    for (int u = 0; u < ILP; ++u) {
        if (!ok[u]) continue;
        float4 vv = v[u], nn = n[u];
        if (flip) {
            float tmp;
            tmp = vv.x; vv.x = vv.w; vv.w = tmp;
            tmp = vv.y; vv.y = vv.z; vv.z = tmp;
            tmp = nn.x; nn.x = nn.w; nn.w = tmp;
            tmp = nn.y; nn.y = nn.z; nn.z = tmp;
        }
        float4 o;
        o.x = aug_one(vv.x, nn.x, bf, cf);
        o.y = aug_one(vv.y, nn.y, bf, cf);
        o.z = aug_one(vv.z, nn.z, bf, cf);
        o.w = aug_one(vv.w, nn.w, bf, cf);
        out[obase + ips[u]] = o;
    }
}

extern "C" void kernel_launch(void* const* d_in, const int* in_sizes, int n_in,
                              void* d_out, int out_size) {
    // metadata order: video, jitter, b_rand, c_rand, noise, flip_rand, drop_rand
    const float* video     = (const float*)d_in[0];
    const int*   jitter    = (const int*)d_in[1];
    const float* b_rand    = (const float*)d_in[2];
    const float* c_rand    = (const float*)d_in[3];
    const float* noise     = (const float*)d_in[4];
    const float* flip_rand = (const float*)d_in[5];
    const float* drop_rand = (const float*)d_in[6];
    float* out = (float*)d_out;

    dim3 grid(GRID_X, BB * CC * TT);   // (13, 768)
    augment_fused<<<grid, THREADS>>>((const float4*)video,
                                     (const float4*)noise,
                                     (float4*)out,
                                     jitter, b_rand, c_rand, flip_rand, drop_rand);
}